// round 11
// baseline (speedup 1.0000x reference)
#include <cuda_runtime.h>

// ctrl_pts: (16,64,64,4) f32 | uspan/vspan: (512,) i32 | Nu/Nv: (512,4) f32
// out: (16,512,512,3) f32
#define BATCH   16
#define MCTRL   64
#define NCTRL   64
#define OUTN    512
#define PDEG    3

typedef unsigned long long ull;

__device__ __forceinline__ ull pack2(float a, float b) {
    ull r; asm("mov.b64 %0, {%1,%2};" : "=l"(r) : "f"(a), "f"(b)); return r;
}
__device__ __forceinline__ void unpack2(ull v, float& a, float& b) {
    asm("mov.b64 {%0,%1}, %2;" : "=f"(a), "=f"(b) : "l"(v));
}
__device__ __forceinline__ ull mul2(ull a, ull b) {
    ull d; asm("mul.rn.f32x2 %0, %1, %2;" : "=l"(d) : "l"(a), "l"(b)); return d;
}
__device__ __forceinline__ ull fma2(ull a, ull b, ull c) {
    ull d; asm("fma.rn.f32x2 %0, %1, %2, %3;" : "=l"(d) : "l"(a), "l"(b), "l"(c)); return d;
}
__device__ __forceinline__ float rcp_approx(float x) {
    float r; asm("rcp.approx.f32 %0, %1;" : "=f"(r) : "f"(x)); return r;
}

// ---------------------------------------------------------------------------
// Fused kernel. Block = (b, 4 u-rows), 128 threads.
// Phase 1: A[4][64] into smem — two entries per thread.
// Phase 2: thread g owns v-quad 4g..4g+3. Weights for the quad are expanded
//          once into a 5-window and f32x2-packed ACROSS v-pairs:
//          wpA[j]=(w_v0[j],w_v1[j]), wpB[j]=(w_v2[j],w_v3[j])  -> 20 regs.
//          A components splatted on the fly. 48B/thread contiguous output
//          -> 3 direct STG.128, no staging.
// ---------------------------------------------------------------------------
__global__ __launch_bounds__(128, 6)
void surf_fused(const float4* __restrict__ ctrl,
                const int*    __restrict__ uspan,
                const int4*   __restrict__ vspan4,
                const float4* __restrict__ Nv4,
                const float4* __restrict__ Nu4,
                float4*       __restrict__ out4)
{
    __shared__ float4 sA[4 * NCTRL];          // 4 KB

    int t  = threadIdx.x;                     // 0..127
    int b  = blockIdx.y;
    int u0 = blockIdx.x * 4;

    // ---- phase-2 weight setup (hoisted: overlaps phase-1 LDGs) ----
    int g = t;                                // v-quad: 4g..4g+3
    int4 vs  = __ldg(vspan4 + g);
    int  iv0 = vs.x - PDEG;

    ull wpA[5], wpB[5];
    {
        float w[4][5];
        int dks[4] = {0, vs.y - vs.x, vs.z - vs.x, vs.w - vs.x};
#pragma unroll
        for (int k = 0; k < 4; k++) {
            float4 nv = __ldg(Nv4 + 4 * g + k);
            bool sh = dks[k] != 0;
            w[k][0] = sh ? 0.0f : nv.x;
            w[k][1] = sh ? nv.x : nv.y;
            w[k][2] = sh ? nv.y : nv.z;
            w[k][3] = sh ? nv.z : nv.w;
            w[k][4] = sh ? nv.w : 0.0f;
        }
#pragma unroll
        for (int j = 0; j < 5; j++) {
            wpA[j] = pack2(w[0][j], w[1][j]);
            wpB[j] = pack2(w[2][j], w[3][j]);
        }
    }

    // ---------------- Phase 1: two A entries per thread ----------------
    {
        int n  = t & (NCTRL - 1);
        int up = t >> 6;                      // 0..1 ; rows up and up+2
#pragma unroll
        for (int half = 0; half < 2; half++) {
            int ul = up + 2 * half;
            int u  = u0 + ul;
            int iu0 = __ldg(uspan + u) - PDEG;
            const float4* __restrict__ base =
                ctrl + ((b * MCTRL + iu0) * NCTRL + n);
            float4 c0 = __ldg(base + 0 * NCTRL);
            float4 c1 = __ldg(base + 1 * NCTRL);
            float4 c2 = __ldg(base + 2 * NCTRL);
            float4 c3 = __ldg(base + 3 * NCTRL);
            float4 nu = __ldg(Nu4 + u);

            float4 acc;
            acc.x = nu.x*c0.x + nu.y*c1.x + nu.z*c2.x + nu.w*c3.x;
            acc.y = nu.x*c0.y + nu.y*c1.y + nu.z*c2.y + nu.w*c3.y;
            acc.z = nu.x*c0.z + nu.y*c1.z + nu.z*c2.z + nu.w*c3.z;
            acc.w = nu.x*c0.w + nu.y*c1.w + nu.z*c2.w + nu.w*c3.w;

            sA[ul * NCTRL + n] = acc;
        }
    }
    __syncthreads();

    // ---------------- Phase 2: v-quad over 4 rows ----------------
#pragma unroll
    for (int i = 0; i < 4; i++) {
        int u = u0 + i;

        const float4* __restrict__ Ab = sA + i * NCTRL + iv0;
        float4 a0 = Ab[0];
        float4 a1 = Ab[1];
        float4 a2 = Ab[2];
        float4 a3 = Ab[3];
        float4 a4 = Ab[4];

        // Accumulate each component for v-pairs (v0,v1) and (v2,v3).
        ull xA, yA, zA, wA, xB, yB, zB, wB;
        {
            ull s0, s1, s2, s3, s4;
            // x
            s0 = pack2(a0.x, a0.x); s1 = pack2(a1.x, a1.x); s2 = pack2(a2.x, a2.x);
            s3 = pack2(a3.x, a3.x); s4 = pack2(a4.x, a4.x);
            xA = mul2(wpA[0], s0); xB = mul2(wpB[0], s0);
            xA = fma2(wpA[1], s1, xA); xB = fma2(wpB[1], s1, xB);
            xA = fma2(wpA[2], s2, xA); xB = fma2(wpB[2], s2, xB);
            xA = fma2(wpA[3], s3, xA); xB = fma2(wpB[3], s3, xB);
            xA = fma2(wpA[4], s4, xA); xB = fma2(wpB[4], s4, xB);
            // y
            s0 = pack2(a0.y, a0.y); s1 = pack2(a1.y, a1.y); s2 = pack2(a2.y, a2.y);
            s3 = pack2(a3.y, a3.y); s4 = pack2(a4.y, a4.y);
            yA = mul2(wpA[0], s0); yB = mul2(wpB[0], s0);
            yA = fma2(wpA[1], s1, yA); yB = fma2(wpB[1], s1, yB);
            yA = fma2(wpA[2], s2, yA); yB = fma2(wpB[2], s2, yB);
            yA = fma2(wpA[3], s3, yA); yB = fma2(wpB[3], s3, yB);
            yA = fma2(wpA[4], s4, yA); yB = fma2(wpB[4], s4, yB);
            // z
            s0 = pack2(a0.z, a0.z); s1 = pack2(a1.z, a1.z); s2 = pack2(a2.z, a2.z);
            s3 = pack2(a3.z, a3.z); s4 = pack2(a4.z, a4.z);
            zA = mul2(wpA[0], s0); zB = mul2(wpB[0], s0);
            zA = fma2(wpA[1], s1, zA); zB = fma2(wpB[1], s1, zB);
            zA = fma2(wpA[2], s2, zA); zB = fma2(wpB[2], s2, zB);
            zA = fma2(wpA[3], s3, zA); zB = fma2(wpB[3], s3, zB);
            zA = fma2(wpA[4], s4, zA); zB = fma2(wpB[4], s4, zB);
            // w
            s0 = pack2(a0.w, a0.w); s1 = pack2(a1.w, a1.w); s2 = pack2(a2.w, a2.w);
            s3 = pack2(a3.w, a3.w); s4 = pack2(a4.w, a4.w);
            wA = mul2(wpA[0], s0); wB = mul2(wpB[0], s0);
            wA = fma2(wpA[1], s1, wA); wB = fma2(wpB[1], s1, wB);
            wA = fma2(wpA[2], s2, wA); wB = fma2(wpB[2], s2, wB);
            wA = fma2(wpA[3], s3, wA); wB = fma2(wpB[3], s3, wB);
            wA = fma2(wpA[4], s4, wA); wB = fma2(wpB[4], s4, wB);
        }

        // Perspective divide (packed), then unpack for the 3 output chunks.
        float d0, d1, d2, d3;
        unpack2(wA, d0, d1);
        unpack2(wB, d2, d3);
        ull invA = pack2(rcp_approx(d0), rcp_approx(d1));
        ull invB = pack2(rcp_approx(d2), rcp_approx(d3));

        float x0, x1, x2, x3, y0, y1, y2, y3, z0, z1, z2, z3;
        unpack2(mul2(xA, invA), x0, x1);
        unpack2(mul2(yA, invA), y0, y1);
        unpack2(mul2(zA, invA), z0, z1);
        unpack2(mul2(xB, invB), x2, x3);
        unpack2(mul2(yB, invB), y2, y3);
        unpack2(mul2(zB, invB), z2, z3);

        // 48B contiguous per thread: 3 STG.128 at stride 48B across lanes.
        float4* __restrict__ o =
            out4 + (size_t)(b * OUTN + u) * (OUTN * 3 / 4) + 3 * g;
        o[0] = make_float4(x0, y0, z0, x1);
        o[1] = make_float4(y1, z1, x2, y2);
        o[2] = make_float4(z2, x3, y3, z3);
    }
}

extern "C" void kernel_launch(void* const* d_in, const int* in_sizes, int n_in,
                              void* d_out, int out_size)
{
    const float4* ctrl   = (const float4*)d_in[0];
    const int*    uspan  = (const int*)   d_in[1];
    const int4*   vspan4 = (const int4*)  d_in[2];
    const float4* Nu4    = (const float4*)d_in[3];
    const float4* Nv4    = (const float4*)d_in[4];
    float4*       out4   = (float4*)      d_out;

    dim3 grid(OUTN / 4, BATCH);               // 128 x 16 = 2048 blocks
    surf_fused<<<grid, 128>>>(ctrl, uspan, vspan4, Nv4, Nu4, out4);
}

// round 12
// speedup vs baseline: 1.1047x; 1.1047x over previous
#include <cuda_runtime.h>

// ctrl_pts: (16,64,64,4) f32 | uspan/vspan: (512,) i32 | Nu/Nv: (512,4) f32
// out: (16,512,512,3) f32
#define BATCH   16
#define MCTRL   64
#define NCTRL   64
#define OUTN    512
#define PDEG    3

typedef unsigned long long ull;

__device__ __forceinline__ ull pack2(float a, float b) {
    ull r; asm("mov.b64 %0, {%1,%2};" : "=l"(r) : "f"(a), "f"(b)); return r;
}
__device__ __forceinline__ void unpack2(ull v, float& a, float& b) {
    asm("mov.b64 {%0,%1}, %2;" : "=f"(a), "=f"(b) : "l"(v));
}
__device__ __forceinline__ ull mul2(ull a, ull b) {
    ull d; asm("mul.rn.f32x2 %0, %1, %2;" : "=l"(d) : "l"(a), "l"(b)); return d;
}
__device__ __forceinline__ ull fma2(ull a, ull b, ull c) {
    ull d; asm("fma.rn.f32x2 %0, %1, %2, %3;" : "=l"(d) : "l"(a), "l"(b), "l"(c)); return d;
}
__device__ __forceinline__ float rcp_approx(float x) {
    float r; asm("rcp.approx.f32 %0, %1;" : "=f"(r) : "f"(x)); return r;
}

// ---------------------------------------------------------------------------
// Fused kernel. Block = (b, 4 u-rows), 256 threads, 6 blocks/SM.
// Phase 1: A[4][64] into smem — one entry per thread.
// Phase 2: thread g owns v-pair (2g, 2g+1). First v's weights are the raw
//          4-window (never shifted within its own pair) -> 9 packed weights.
//          A-window consumed as xy then zw LDS.64 halves (low reg pressure).
// Stores:  2 rows staged per warp (1536B) -> 3 full-warp STG.128 across the
//          two contiguous output rows (full 32B sectors).
// ---------------------------------------------------------------------------
__global__ __launch_bounds__(256, 6)
void surf_fused(const float4* __restrict__ ctrl,
                const int*    __restrict__ uspan,
                const int2*   __restrict__ vspan2,
                const float4* __restrict__ Nu4,
                const float4* __restrict__ Nv4,
                float4*       __restrict__ out4)
{
    __shared__ float4 sA[4 * NCTRL];                     // 4 KB
    __shared__ __align__(16) float2 sOut[8][192];        // 8 warps x 1536 B

    int t  = threadIdx.x;                     // 0..255
    int b  = blockIdx.y;
    int u0 = blockIdx.x * 4;
    int lane = t & 31;
    int wrp  = t >> 5;

    // ---- phase-2 weight setup (hoisted: overlaps phase-1 LDGs) ----
    int g = t;
    int2 vs  = __ldg(vspan2 + g);
    int  iv0 = vs.x - PDEG;
    bool sh  = vs.y != vs.x;

    ull wp0[4], wp1[5];
    {
        float4 nv0 = __ldg(Nv4 + 2 * g);
        float4 nv1 = __ldg(Nv4 + 2 * g + 1);
        wp0[0] = pack2(nv0.x, nv0.x);
        wp0[1] = pack2(nv0.y, nv0.y);
        wp0[2] = pack2(nv0.z, nv0.z);
        wp0[3] = pack2(nv0.w, nv0.w);
        float w0 = sh ? 0.0f : nv1.x;
        float w1 = sh ? nv1.x : nv1.y;
        float w2 = sh ? nv1.y : nv1.z;
        float w3 = sh ? nv1.z : nv1.w;
        float w4 = sh ? nv1.w : 0.0f;
        wp1[0] = pack2(w0, w0);
        wp1[1] = pack2(w1, w1);
        wp1[2] = pack2(w2, w2);
        wp1[3] = pack2(w3, w3);
        wp1[4] = pack2(w4, w4);
    }

    // ---------------- Phase 1: one A entry per thread ----------------
    {
        int n  = t & (NCTRL - 1);
        int ul = t >> 6;                      // 0..3
        int u  = u0 + ul;
        int iu0 = __ldg(uspan + u) - PDEG;
        const float4* __restrict__ base =
            ctrl + ((b * MCTRL + iu0) * NCTRL + n);
        float4 c0 = __ldg(base + 0 * NCTRL);
        float4 c1 = __ldg(base + 1 * NCTRL);
        float4 c2 = __ldg(base + 2 * NCTRL);
        float4 c3 = __ldg(base + 3 * NCTRL);
        float4 nu = __ldg(Nu4 + u);

        float4 acc;
        acc.x = nu.x*c0.x + nu.y*c1.x + nu.z*c2.x + nu.w*c3.x;
        acc.y = nu.x*c0.y + nu.y*c1.y + nu.z*c2.y + nu.w*c3.y;
        acc.z = nu.x*c0.z + nu.y*c1.z + nu.z*c2.z + nu.w*c3.z;
        acc.w = nu.x*c0.w + nu.y*c1.w + nu.z*c2.w + nu.w*c3.w;

        sA[ul * NCTRL + n] = acc;
    }
    __syncthreads();

    // ---------------- Phase 2: v-pair (2g, 2g+1), rows in pairs ----------------
    float2* __restrict__ sb = sOut[wrp];

#pragma unroll
    for (int ip = 0; ip < 2; ip++) {
        if (ip) __syncwarp();                 // prior readback done

#pragma unroll
        for (int ir = 0; ir < 2; ir++) {
            int i = 2 * ip + ir;
            // A window base for this row; xy at even ull slots, zw at odd.
            const ull* __restrict__ Ab = (const ull*)(sA + i * NCTRL + iv0);

            // ---- xy halves ----
            ull h0 = Ab[0], h1 = Ab[2], h2 = Ab[4], h3 = Ab[6], h4 = Ab[8];
            ull xy0 = mul2(wp0[0], h0);
            ull xy1 = mul2(wp1[0], h0);
            xy0 = fma2(wp0[1], h1, xy0);  xy1 = fma2(wp1[1], h1, xy1);
            xy0 = fma2(wp0[2], h2, xy0);  xy1 = fma2(wp1[2], h2, xy1);
            xy0 = fma2(wp0[3], h3, xy0);  xy1 = fma2(wp1[3], h3, xy1);
            /* wp0[4] == 0: elided */      xy1 = fma2(wp1[4], h4, xy1);

            // ---- zw halves ----
            h0 = Ab[1]; h1 = Ab[3]; h2 = Ab[5]; h3 = Ab[7]; h4 = Ab[9];
            ull zw0 = mul2(wp0[0], h0);
            ull zw1 = mul2(wp1[0], h0);
            zw0 = fma2(wp0[1], h1, zw0);  zw1 = fma2(wp1[1], h1, zw1);
            zw0 = fma2(wp0[2], h2, zw0);  zw1 = fma2(wp1[2], h2, zw1);
            zw0 = fma2(wp0[3], h3, zw0);  zw1 = fma2(wp1[3], h3, zw1);
                                          zw1 = fma2(wp1[4], h4, zw1);

            float sx, sy, sz, sw, inv;
            float2* __restrict__ row = sb + ir * 96 + 3 * lane;
            unpack2(zw0, sz, sw);
            inv = rcp_approx(sw);
            unpack2(xy0, sx, sy);
            row[0] = make_float2(sx * inv, sy * inv);
            float z0 = sz * inv;
            unpack2(zw1, sz, sw);
            inv = rcp_approx(sw);
            unpack2(xy1, sx, sy);
            row[1] = make_float2(z0, sx * inv);
            row[2] = make_float2(sy * inv, sz * inv);
        }
        __syncwarp();

        // Write 2 contiguous rows' worth (96 float4) with 3 full STG.128.
        const float4* __restrict__ sb4 = (const float4*)sb;
        float4* __restrict__ rowp =
            out4 + (size_t)(b * OUTN + u0 + 2 * ip) * (OUTN * 3 / 4) + wrp * 48;
        // staged float4 m: m<48 -> row (2ip) + m ; else row (2ip+1) + (m-48)
        // row stride = 384 float4, so else-branch offset = m + 336.
#pragma unroll
        for (int s = 0; s < 3; s++) {
            int m = s * 32 + lane;
            rowp[m < 48 ? m : m + 336] = sb4[m];
        }
    }
}

extern "C" void kernel_launch(void* const* d_in, const int* in_sizes, int n_in,
                              void* d_out, int out_size)
{
    const float4* ctrl   = (const float4*)d_in[0];
    const int*    uspan  = (const int*)   d_in[1];
    const int2*   vspan2 = (const int2*)  d_in[2];
    const float4* Nu4    = (const float4*)d_in[3];
    const float4* Nv4    = (const float4*)d_in[4];
    float4*       out4   = (float4*)      d_out;

    dim3 grid(OUTN / 4, BATCH);               // 128 x 16 = 2048 blocks
    surf_fused<<<grid, 256>>>(ctrl, uspan, vspan2, Nu4, Nv4, out4);
}

// round 13
// speedup vs baseline: 1.1214x; 1.0152x over previous
#include <cuda_runtime.h>

// ctrl_pts: (16,64,64,4) f32 | uspan/vspan: (512,) i32 | Nu/Nv: (512,4) f32
// out: (16,512,512,3) f32
#define BATCH   16
#define MCTRL   64
#define NCTRL   64
#define OUTN    512
#define PDEG    3

typedef unsigned long long ull;

__device__ __forceinline__ ull pack2(float a, float b) {
    ull r; asm("mov.b64 %0, {%1,%2};" : "=l"(r) : "f"(a), "f"(b)); return r;
}
__device__ __forceinline__ void unpack2(ull v, float& a, float& b) {
    asm("mov.b64 {%0,%1}, %2;" : "=f"(a), "=f"(b) : "l"(v));
}
__device__ __forceinline__ ull mul2(ull a, ull b) {
    ull d; asm("mul.rn.f32x2 %0, %1, %2;" : "=l"(d) : "l"(a), "l"(b)); return d;
}
__device__ __forceinline__ ull fma2(ull a, ull b, ull c) {
    ull d; asm("fma.rn.f32x2 %0, %1, %2, %3;" : "=l"(d) : "l"(a), "l"(b), "l"(c)); return d;
}
__device__ __forceinline__ float rcp_approx(float x) {
    float r; asm("rcp.approx.f32 %0, %1;" : "=f"(r) : "f"(x)); return r;
}

// ---------------------------------------------------------------------------
// Fused kernel. Block = (b, 4 u-rows), 256 threads, 5 blocks/SM.
// Phase 1: A[4][64] into smem — one entry per thread.
// Phase 2: thread g owns v-pair (2g, 2g+1). 9 packed weights (first v's
//          window is never shifted -> 4 taps; second v 5 taps).
//          A window loaded as 5 LDS.128 (broadcast-heavy). Packed epilogue.
// Stores:  2 rows staged per warp (1536B) -> 3 full-warp STG.128 rounds.
// ---------------------------------------------------------------------------
__global__ __launch_bounds__(256, 5)
void surf_fused(const float4* __restrict__ ctrl,
                const int*    __restrict__ uspan,
                const int2*   __restrict__ vspan2,
                const float4* __restrict__ Nu4,
                const float4* __restrict__ Nv4,
                float4*       __restrict__ out4)
{
    __shared__ float4 sA[4 * NCTRL];                     // 4 KB
    __shared__ __align__(16) ull sOut[8][192];           // 8 warps x 1536 B

    int t  = threadIdx.x;                     // 0..255
    int b  = blockIdx.y;
    int u0 = blockIdx.x * 4;
    int lane = t & 31;
    int wrp  = t >> 5;

    // ---- phase-2 weight setup (hoisted: overlaps phase-1 LDGs) ----
    int g = t;
    int2 vs  = __ldg(vspan2 + g);
    int  iv0 = vs.x - PDEG;
    bool sh  = vs.y != vs.x;

    ull wp0[4], wp1[5];
    {
        float4 nv0 = __ldg(Nv4 + 2 * g);
        float4 nv1 = __ldg(Nv4 + 2 * g + 1);
        wp0[0] = pack2(nv0.x, nv0.x);
        wp0[1] = pack2(nv0.y, nv0.y);
        wp0[2] = pack2(nv0.z, nv0.z);
        wp0[3] = pack2(nv0.w, nv0.w);
        float w0 = sh ? 0.0f : nv1.x;
        float w1 = sh ? nv1.x : nv1.y;
        float w2 = sh ? nv1.y : nv1.z;
        float w3 = sh ? nv1.z : nv1.w;
        float w4 = sh ? nv1.w : 0.0f;
        wp1[0] = pack2(w0, w0);
        wp1[1] = pack2(w1, w1);
        wp1[2] = pack2(w2, w2);
        wp1[3] = pack2(w3, w3);
        wp1[4] = pack2(w4, w4);
    }

    // ---------------- Phase 1: one A entry per thread ----------------
    {
        int n  = t & (NCTRL - 1);
        int ul = t >> 6;                      // 0..3
        int u  = u0 + ul;
        int iu0 = __ldg(uspan + u) - PDEG;
        const float4* __restrict__ base =
            ctrl + ((b * MCTRL + iu0) * NCTRL + n);
        float4 c0 = __ldg(base + 0 * NCTRL);
        float4 c1 = __ldg(base + 1 * NCTRL);
        float4 c2 = __ldg(base + 2 * NCTRL);
        float4 c3 = __ldg(base + 3 * NCTRL);
        float4 nu = __ldg(Nu4 + u);

        float4 acc;
        acc.x = nu.x*c0.x + nu.y*c1.x + nu.z*c2.x + nu.w*c3.x;
        acc.y = nu.x*c0.y + nu.y*c1.y + nu.z*c2.y + nu.w*c3.y;
        acc.z = nu.x*c0.z + nu.y*c1.z + nu.z*c2.z + nu.w*c3.z;
        acc.w = nu.x*c0.w + nu.y*c1.w + nu.z*c2.w + nu.w*c3.w;

        sA[ul * NCTRL + n] = acc;
    }
    __syncthreads();

    // ---------------- Phase 2: v-pair (2g, 2g+1), rows in pairs ----------------
    ull* __restrict__ sb = sOut[wrp];

#pragma unroll
    for (int ip = 0; ip < 2; ip++) {
        if (ip) __syncwarp();                 // prior readback done

#pragma unroll
        for (int ir = 0; ir < 2; ir++) {
            int i = 2 * ip + ir;
            const ulonglong2* __restrict__ Ab =
                (const ulonglong2*)(sA + i * NCTRL + iv0);
            ulonglong2 A0 = Ab[0];
            ulonglong2 A1 = Ab[1];
            ulonglong2 A2 = Ab[2];
            ulonglong2 A3 = Ab[3];
            ulonglong2 A4 = Ab[4];

            // v0: 4 taps (window never shifted for first v of the pair)
            ull xy0 = mul2(wp0[0], A0.x);
            ull zw0 = mul2(wp0[0], A0.y);
            xy0 = fma2(wp0[1], A1.x, xy0);  zw0 = fma2(wp0[1], A1.y, zw0);
            xy0 = fma2(wp0[2], A2.x, xy0);  zw0 = fma2(wp0[2], A2.y, zw0);
            xy0 = fma2(wp0[3], A3.x, xy0);  zw0 = fma2(wp0[3], A3.y, zw0);

            // v1: 5 taps
            ull xy1 = mul2(wp1[0], A0.x);
            ull zw1 = mul2(wp1[0], A0.y);
            xy1 = fma2(wp1[1], A1.x, xy1);  zw1 = fma2(wp1[1], A1.y, zw1);
            xy1 = fma2(wp1[2], A2.x, xy1);  zw1 = fma2(wp1[2], A2.y, zw1);
            xy1 = fma2(wp1[3], A3.x, xy1);  zw1 = fma2(wp1[3], A3.y, zw1);
            xy1 = fma2(wp1[4], A4.x, xy1);  zw1 = fma2(wp1[4], A4.y, zw1);

            // Packed epilogue.
            float sz0, sw0, sz1, sw1;
            unpack2(zw0, sz0, sw0);
            unpack2(zw1, sz1, sw1);
            float inv0 = rcp_approx(sw0);
            float inv1 = rcp_approx(sw1);

            ull c0 = mul2(xy0, pack2(inv0, inv0));     // (x0', y0')
            ull xy1s = mul2(xy1, pack2(inv1, inv1));
            float x1s, y1s;
            unpack2(xy1s, x1s, y1s);
            ull c1 = pack2(sz0 * inv0, x1s);           // (z0', x1')
            ull c2 = pack2(y1s, sz1 * inv1);           // (y1', z1')

            ull* __restrict__ rp = sb + ir * 96 + 3 * lane;
            rp[0] = c0;
            rp[1] = c1;
            rp[2] = c2;
        }
        __syncwarp();

        // Write 2 contiguous rows' worth (96 float4) with 3 full STG.128.
        const float4* __restrict__ sb4 = (const float4*)sb;
        float4* __restrict__ rowp =
            out4 + (size_t)(b * OUTN + u0 + 2 * ip) * (OUTN * 3 / 4) + wrp * 48;
        // staged float4 m: m<48 -> row (2ip)+m ; else row (2ip+1)+(m-48);
        // row stride = 384 float4 -> else-offset = m + 336.
#pragma unroll
        for (int s = 0; s < 3; s++) {
            int m = s * 32 + lane;
            rowp[m < 48 ? m : m + 336] = sb4[m];
        }
    }
}

extern "C" void kernel_launch(void* const* d_in, const int* in_sizes, int n_in,
                              void* d_out, int out_size)
{
    const float4* ctrl   = (const float4*)d_in[0];
    const int*    uspan  = (const int*)   d_in[1];
    const int2*   vspan2 = (const int2*)  d_in[2];
    const float4* Nu4    = (const float4*)d_in[3];
    const float4* Nv4    = (const float4*)d_in[4];
    float4*       out4   = (float4*)      d_out;

    dim3 grid(OUTN / 4, BATCH);               // 128 x 16 = 2048 blocks
    surf_fused<<<grid, 256>>>(ctrl, uspan, vspan2, Nu4, Nv4, out4);
}